// round 7
// baseline (speedup 1.0000x reference)
#include <cuda_runtime.h>
#include <cstdint>

#define B_      2
#define I_      1024
#define J_      1024
#define C_      64
#define TJ      32
#define NT      (J_/TJ)     // 32
#define ROWS    2
#define THREADS 64
#define KPAD    17          // float4 per K row in smem (conflict-free)

__device__ __forceinline__ uint32_t pack_h2(float hi, float lo) {
    uint32_t p;
    asm("cvt.rn.f16x2.f32 %0, %1, %2;" : "=r"(p) : "f"(hi), "f"(lo));
    return p;
}
__device__ __forceinline__ uint32_t tanh_h2(uint32_t x) {
    uint32_t y;
    asm("tanh.approx.f16x2 %0, %1;" : "=r"(y) : "r"(x));
    return y;
}
__device__ __forceinline__ void unpack_h2(uint32_t p, float& lo, float& hi) {
    asm("{\n\t.reg .b16 l, h;\n\tmov.b32 {l, h}, %2;\n\t"
        "cvt.f32.f16 %0, l;\n\tcvt.f32.f16 %1, h;\n\t}"
        : "=f"(lo), "=f"(hi) : "r"(p));
}
__device__ __forceinline__ void cp16(uint32_t s, const void* g) {
    asm volatile("cp.async.cg.shared.global [%0], [%1], 16;" :: "r"(s), "l"(g));
}
__device__ __forceinline__ void cp_commit() { asm volatile("cp.async.commit_group;"); }
template<int N> __device__ __forceinline__ void cp_wait() {
    asm volatile("cp.async.wait_group %0;" :: "n"(N));
}

__global__ __launch_bounds__(THREADS, 7)
void fused_attn_mlp_kernel(const float* __restrict__ Q,
                           const float* __restrict__ K,
                           const float* __restrict__ bias,
                           const float* __restrict__ mask,
                           float* __restrict__ out,      // [B,I,C]
                           float* __restrict__ attn)     // [B,I,J]
{
    __shared__ __align__(16) float4 kbuf[2][TJ * KPAD];   // 2 x 8.7KB
    __shared__ __align__(16) float4 sbv[16];              // 0.5*bias

    const int tid  = threadIdx.x;
    const int lane = tid & 31;
    const int w    = tid >> 5;            // warp = local row (0/1)
    const int half = lane >> 4;           // 0: ch 0-31, 1: ch 32-63
    const int lj   = lane & 15;           // j subgroup index
    const int row  = blockIdx.x * ROWS + w;
    const int b    = row >> 10;
    const int h8   = half * 8;            // float4 offset of this channel half

    if (tid < C_) ((float*)sbv)[tid] = 0.5f * bias[tid];

    const uint32_t sb0 = (uint32_t)__cvta_generic_to_shared(&kbuf[0][0]);
    const uint32_t sb1 = (uint32_t)__cvta_generic_to_shared(&kbuf[1][0]);
    const float4* Kb = (const float4*)K + (size_t)b * J_ * 16;

    // prefetch tile 0: TJ*16 = 512 float4 / 64 thr = 8 per thread
    #pragma unroll
    for (int p = 0; p < (TJ * 16) / THREADS; ++p) {
        int idx = tid + p * THREADS;
        int r = idx >> 4, c = idx & 15;
        cp16(sb0 + (uint32_t)(r * KPAD + c) * 16, Kb + (size_t)r * 16 + c);
    }
    cp_commit();

    // q-half straight to registers
    float4 qh[8];
    {
        const float4* qrow = (const float4*)(Q + (size_t)row * C_) + h8;
        #pragma unroll
        for (int c = 0; c < 8; ++c) {
            float4 v = qrow[c];
            qh[c] = make_float4(0.5f*v.x, 0.5f*v.y, 0.5f*v.z, 0.5f*v.w);
        }
    }

    __syncthreads();   // sbv visible

    float ssum = 0.f;
    #pragma unroll
    for (int c = 0; c < C_; ++c) ssum += ((const float*)sbv)[c];

    const float4* bp = &sbv[h8];

    float4 acc[8];
    #pragma unroll
    for (int c = 0; c < 8; ++c) acc[c] = make_float4(0.f, 0.f, 0.f, 0.f);
    float msum = 0.f;

    const float* mrow = mask + (size_t)row * J_;
    float*       arow = attn + (size_t)row * J_;

    for (int t = 0; t < NT; ++t) {
        const float m0 = mrow[t * TJ + lj];
        const float m1 = mrow[t * TJ + 16 + lj];

        if (t + 1 < NT) {
            const float4* src = Kb + (size_t)(t + 1) * TJ * 16;
            uint32_t dst = ((t + 1) & 1) ? sb1 : sb0;
            #pragma unroll
            for (int p = 0; p < (TJ * 16) / THREADS; ++p) {
                int idx = tid + p * THREADS;
                int r = idx >> 4, c = idx & 15;
                cp16(dst + (uint32_t)(r * KPAD + c) * 16, src + (size_t)r * 16 + c);
            }
            cp_commit();
            cp_wait<1>();
        } else {
            cp_wait<0>();
        }
        __syncthreads();

        const float4* kb = kbuf[t & 1];

        #pragma unroll
        for (int u = 0; u < 2; ++u) {
            const int jj = u * 16 + lj;
            const float m  = (u == 0) ? m0 : m1;
            const float mh = 0.5f * m;
            const float4* kr = kb + jj * KPAD + h8;

            float hs0 = 0.f, hs1 = 0.f, hs2 = 0.f, hs3 = 0.f;
            #pragma unroll
            for (int c = 0; c < 8; ++c) {
                const float4 k4 = kr[c];
                const float4 b4 = bp[c];
                const float h0 = fmaf(qh[c].x, k4.x, b4.x);
                const float h1 = fmaf(qh[c].y, k4.y, b4.y);
                const float h2 = fmaf(qh[c].z, k4.z, b4.z);
                const float h3 = fmaf(qh[c].w, k4.w, b4.w);
                hs0 += h0; hs1 += h1; hs2 += h2; hs3 += h3;
                // packed-half tanh: 2 tanhs per MUFU op
                const uint32_t t01 = tanh_h2(pack_h2(h1, h0));
                const uint32_t t23 = tanh_h2(pack_h2(h3, h2));
                float t0, t1, t2, t3;
                unpack_h2(t01, t0, t1);
                unpack_h2(t23, t2, t3);
                acc[c].x = fmaf(t0, mh, acc[c].x);
                acc[c].y = fmaf(t1, mh, acc[c].y);
                acc[c].z = fmaf(t2, mh, acc[c].z);
                acc[c].w = fmaf(t3, mh, acc[c].w);
            }
            float hs = (hs0 + hs1) + (hs2 + hs3);       // this half's 32-ch sum (fp32)
            hs += __shfl_xor_sync(0xffffffffu, hs, 16); // full 64-ch sum
            if (half == 0) arow[t * TJ + jj] = 2.0f * (hs - ssum) * m;
            msum += m;
        }
        __syncthreads();
    }

    // reduce over the 16 lj lanes (channel halves stay separate)
    #pragma unroll
    for (int s = 1; s < 16; s <<= 1) {
        msum += __shfl_xor_sync(0xffffffffu, msum, s);
        #pragma unroll
        for (int c = 0; c < 8; ++c) {
            acc[c].x += __shfl_xor_sync(0xffffffffu, acc[c].x, s);
            acc[c].y += __shfl_xor_sync(0xffffffffu, acc[c].y, s);
            acc[c].z += __shfl_xor_sync(0xffffffffu, acc[c].z, s);
            acc[c].w += __shfl_xor_sync(0xffffffffu, acc[c].w, s);
        }
    }

    if (lj == 0) {   // lane 0 writes ch 0-31, lane 16 writes ch 32-63
        const float hm  = 0.5f * msum;
        const float inv = __fdividef(1.0f, msum);
        float* orow = out + (size_t)row * C_ + half * 32;
        #pragma unroll
        for (int c = 0; c < 8; ++c) {
            float4 o;
            o.x = (acc[c].x + hm) * inv;
            o.y = (acc[c].y + hm) * inv;
            o.z = (acc[c].z + hm) * inv;
            o.w = (acc[c].w + hm) * inv;
            *(float4*)(orow + c * 4) = o;
        }
    }
}

extern "C" void kernel_launch(void* const* d_in, const int* in_sizes, int n_in,
                              void* d_out, int out_size) {
    const float* Q    = (const float*)d_in[0];
    const float* K    = (const float*)d_in[1];
    const float* bias = (const float*)d_in[2];
    const float* mask = (const float*)d_in[3];
    float* out  = (float*)d_out;                       // [B,I,C] first
    float* attn = (float*)d_out + (size_t)B_*I_*C_;    // [B,I,J] second

    dim3 grid(B_ * I_ / ROWS);
    dim3 block(THREADS);
    fused_attn_mlp_kernel<<<grid, block>>>(Q, K, bias, mask, out, attn);
}

// round 8
// speedup vs baseline: 1.0713x; 1.0713x over previous
#include <cuda_runtime.h>
#include <cstdint>

#define B_      2
#define I_      1024
#define J_      1024
#define C_      64
#define JSPLIT  2
#define JHALF   (J_/JSPLIT)   // 512
#define TJ      32
#define NT      (JHALF/TJ)    // 16 tiles per block
#define ROWS    2
#define THREADS 64
#define KPAD    17            // float4 per K row in smem

// cross-block partial accumulators (j-split halves)
__device__ float g_part[JSPLIT][B_*I_][C_];
__device__ float g_msum[JSPLIT][B_*I_];

__device__ __forceinline__ float tanh_apx(float x) {
    float y; asm("tanh.approx.f32 %0, %1;" : "=f"(y) : "f"(x)); return y;
}
__device__ __forceinline__ void cp16(uint32_t s, const void* g) {
    asm volatile("cp.async.cg.shared.global [%0], [%1], 16;" :: "r"(s), "l"(g));
}
__device__ __forceinline__ void cp_commit() { asm volatile("cp.async.commit_group;"); }
template<int N> __device__ __forceinline__ void cp_wait() {
    asm volatile("cp.async.wait_group %0;" :: "n"(N));
}

__global__ __launch_bounds__(THREADS, 12)
void fused_pass1(const float* __restrict__ Q,
                 const float* __restrict__ K,
                 const float* __restrict__ bias,
                 const float* __restrict__ mask,
                 float* __restrict__ attn)     // [B,I,J]
{
    __shared__ __align__(16) float4 kbuf[2][TJ * KPAD];   // 2 x 8.7KB

    const int tid   = threadIdx.x;
    const int lane  = tid & 31;
    const int w     = tid >> 5;           // warp = local row (0/1)
    const int lj8   = lane & 7;           // j within 8-group
    const int qtr   = lane >> 3;          // channel quarter (16 ch)
    const int bid   = blockIdx.x;
    const int jh    = bid & 1;            // j-half
    const int rowbk = bid >> 1;           // row pair index
    const int row   = rowbk * ROWS + w;
    const int b     = (rowbk * ROWS) >> 10;
    const int q4    = qtr * 4;            // float4 offset of this quarter

    const uint32_t sb0 = (uint32_t)__cvta_generic_to_shared(&kbuf[0][0]);
    const uint32_t sb1 = (uint32_t)__cvta_generic_to_shared(&kbuf[1][0]);
    const float4* Kb = (const float4*)K + ((size_t)b * J_ + jh * JHALF) * 16;

    // prefetch tile 0: TJ*16 = 512 float4 / 64 thr = 8 per thread
    #pragma unroll
    for (int p = 0; p < (TJ * 16) / THREADS; ++p) {
        int idx = tid + p * THREADS;
        int r = idx >> 4, c = idx & 15;
        cp16(sb0 + (uint32_t)(r * KPAD + c) * 16, Kb + (size_t)r * 16 + c);
    }
    cp_commit();

    // q and bias quarters -> registers (16 channels each)
    float4 qh[4], bh[4];
    {
        const float4* qrow = (const float4*)(Q + (size_t)row * C_) + q4;
        const float4* brow = (const float4*)bias + q4;
        #pragma unroll
        for (int c = 0; c < 4; ++c) {
            float4 v = qrow[c];
            qh[c] = make_float4(0.5f*v.x, 0.5f*v.y, 0.5f*v.z, 0.5f*v.w);
            float4 u = brow[c];
            bh[c] = make_float4(0.5f*u.x, 0.5f*u.y, 0.5f*u.z, 0.5f*u.w);
        }
    }
    // ssum = 0.5 * sum(bias): quarter-local sum then combine across quarters
    float ssum;
    {
        float s = 0.f;
        #pragma unroll
        for (int c = 0; c < 4; ++c) s += (bh[c].x + bh[c].y) + (bh[c].z + bh[c].w);
        s += __shfl_xor_sync(0xffffffffu, s, 8);
        s += __shfl_xor_sync(0xffffffffu, s, 16);
        ssum = s;
    }

    float4 acc[4];
    #pragma unroll
    for (int c = 0; c < 4; ++c) acc[c] = make_float4(0.f, 0.f, 0.f, 0.f);
    float msum = 0.f;

    const float* mrow = mask + (size_t)row * J_ + jh * JHALF;
    float*       arow = attn + (size_t)row * J_ + jh * JHALF;

    for (int t = 0; t < NT; ++t) {
        // masks for this tile (one j per lane per u-iter; quarters duplicate)
        float ma[4];
        #pragma unroll
        for (int u = 0; u < 4; ++u) ma[u] = mrow[t * TJ + u * 8 + lj8];

        if (t + 1 < NT) {
            const float4* src = Kb + (size_t)(t + 1) * TJ * 16;
            uint32_t dst = ((t + 1) & 1) ? sb1 : sb0;
            #pragma unroll
            for (int p = 0; p < (TJ * 16) / THREADS; ++p) {
                int idx = tid + p * THREADS;
                int r = idx >> 4, c = idx & 15;
                cp16(dst + (uint32_t)(r * KPAD + c) * 16, src + (size_t)r * 16 + c);
            }
            cp_commit();
            cp_wait<1>();
        } else {
            cp_wait<0>();
        }
        __syncthreads();

        const float4* kb = kbuf[t & 1];

        #pragma unroll
        for (int u = 0; u < 4; ++u) {
            const int jj = u * 8 + lj8;
            const float m  = ma[u];
            const float mh = 0.5f * m;
            const float4* kr = kb + jj * KPAD + q4;

            float hs0 = 0.f, hs1 = 0.f, hs2 = 0.f, hs3 = 0.f;
            #pragma unroll
            for (int c = 0; c < 4; ++c) {
                const float4 k4 = kr[c];
                const float h0 = fmaf(qh[c].x, k4.x, bh[c].x);
                const float h1 = fmaf(qh[c].y, k4.y, bh[c].y);
                const float h2 = fmaf(qh[c].z, k4.z, bh[c].z);
                const float h3 = fmaf(qh[c].w, k4.w, bh[c].w);
                hs0 += h0; hs1 += h1; hs2 += h2; hs3 += h3;
                acc[c].x = fmaf(tanh_apx(h0), mh, acc[c].x);
                acc[c].y = fmaf(tanh_apx(h1), mh, acc[c].y);
                acc[c].z = fmaf(tanh_apx(h2), mh, acc[c].z);
                acc[c].w = fmaf(tanh_apx(h3), mh, acc[c].w);
            }
            float hs = (hs0 + hs1) + (hs2 + hs3);       // 16-ch partial
            hs += __shfl_xor_sync(0xffffffffu, hs, 8);  // combine quarters
            hs += __shfl_xor_sync(0xffffffffu, hs, 16);
            if (lane < 8) arow[t * TJ + u * 8 + lane] = 2.0f * (hs - ssum) * m;
            msum += m;
        }
        __syncthreads();
    }

    // reduce acc over the 8 j-lanes of each quarter
    #pragma unroll
    for (int s = 1; s < 8; s <<= 1) {
        #pragma unroll
        for (int c = 0; c < 4; ++c) {
            acc[c].x += __shfl_xor_sync(0xffffffffu, acc[c].x, s);
            acc[c].y += __shfl_xor_sync(0xffffffffu, acc[c].y, s);
            acc[c].z += __shfl_xor_sync(0xffffffffu, acc[c].z, s);
            acc[c].w += __shfl_xor_sync(0xffffffffu, acc[c].w, s);
        }
    }
    // msum full reduce (quarters count 4x; scale by 0.25)
    #pragma unroll
    for (int s = 1; s < 32; s <<= 1)
        msum += __shfl_xor_sync(0xffffffffu, msum, s);

    if (lj8 == 0) {   // lanes 0,8,16,24: write this quarter's partial
        float4* dst = (float4*)&g_part[jh][row][qtr * 16];
        #pragma unroll
        for (int c = 0; c < 4; ++c) dst[c] = acc[c];
        if (qtr == 0) g_msum[jh][row] = 0.25f * msum;
    }
}

__global__ void fused_pass2(float* __restrict__ out)   // [B,I,C]
{
    const int idx = blockIdx.x * blockDim.x + threadIdx.x;   // 0 .. 2048*64-1
    const int r  = idx >> 6;
    const int ch = idx & 63;
    const float ms = g_msum[0][r] + g_msum[1][r];
    const float v  = g_part[0][r][ch] + g_part[1][r][ch];
    out[idx] = (v + 0.5f * ms) * __fdividef(1.0f, ms);
}

extern "C" void kernel_launch(void* const* d_in, const int* in_sizes, int n_in,
                              void* d_out, int out_size) {
    const float* Q    = (const float*)d_in[0];
    const float* K    = (const float*)d_in[1];
    const float* bias = (const float*)d_in[2];
    const float* mask = (const float*)d_in[3];
    float* out  = (float*)d_out;                       // [B,I,C] first
    float* attn = (float*)d_out + (size_t)B_*I_*C_;    // [B,I,J] second

    fused_pass1<<<(B_ * I_ / ROWS) * JSPLIT, THREADS>>>(Q, K, bias, mask, attn);
    fused_pass2<<<(B_ * I_ * C_) / 256, 256>>>(out);
}